// round 4
// baseline (speedup 1.0000x reference)
#include <cuda_runtime.h>
#include <cstdint>
#include <cstddef>

// Problem constants
#define EHID 128
#define EINT 64
#define NBAS 8
#define NNR 6
#define NSBF 42      // NS*NR = 7*6
#define NE 200000
#define NT 2000000

// Scratch buffers (device globals; no allocation allowed)
__device__ __align__(128) float g_bufA[NE * EHID];  // x_ji, then res-block temp
__device__ __align__(128) float g_bufB[NE * EHID];  // t (kj*rbf), then h
__device__ __align__(128) float g_bufC[NE * EINT];  // x_kj after down
__device__ __align__(128) float g_bufD[NE * EINT];  // agg (segment sum)

__device__ __forceinline__ float swishf(float v) {
    return v / (1.0f + __expf(-v));
}

// ---------------------------------------------------------------------------
// Generic small-N GEMM: out[M,N] = epi(A[M,K] @ W[K,N])
// epi: (+bias) -> (swish) -> (*rbf_e) -> (+addsrc)
// Block: 256 threads computes a 64-row x N tile. Register tile 4 x (N/16).
// In-place A==out is safe: each block reads only its own 64 rows across the
// whole K loop and writes them only in the epilogue.
// ---------------------------------------------------------------------------
template<int N, int K, bool BIAS, bool ACT, bool ADD, bool RBF>
__global__ __launch_bounds__(256)
void gemm_k(const float* __restrict__ A, const float* __restrict__ W,
            const float* __restrict__ bias, const float* __restrict__ addsrc,
            const float* __restrict__ rbf, const float* __restrict__ wrbf1,
            const float* __restrict__ wrbf2,
            float* __restrict__ out, int M)
{
    constexpr int MT = 64;
    constexpr int BK = 32;
    constexpr int TN = N / 16;          // 8 for N=128, 4 for N=64
    static_assert(N % 16 == 0 && K % BK == 0, "shape");

    __shared__ float As[BK * MT];       // transposed: As[k][row]
    __shared__ float Ws[BK * N];        // Ws[k][n]
    __shared__ float r8s[RBF ? (MT * 8) : 1];
    __shared__ float w2s[RBF ? (8 * 128) : 1];

    const int tid = threadIdx.x;
    const int m0  = blockIdx.x * MT;
    const int r0  = (tid >> 4) * 4;     // row within tile
    const int c0  = (tid & 15) * TN;    // col

    // RBF prologue: r8[row] = rbf[row, :6] @ wrbf1[6,8]; stage wrbf2[8,128]
    if (RBF) {
        #pragma unroll
        for (int u = 0; u < 4; u++) {
            int idx = tid + u * 256;
            w2s[idx] = wrbf2[idx];
        }
        #pragma unroll
        for (int u = 0; u < 2; u++) {
            int idx = tid + u * 256;    // 512 = 64 rows * 8
            int row = idx >> 3, jj = idx & 7;
            int grow = m0 + row;
            float s = 0.f;
            if (grow < M) {
                #pragma unroll
                for (int i = 0; i < NNR; i++)
                    s += rbf[(size_t)grow * NNR + i] * wrbf1[i * 8 + jj];
            }
            r8s[row * 8 + jj] = s;
        }
    }

    float acc[4 * TN];
    #pragma unroll
    for (int i = 0; i < 4 * TN; i++) acc[i] = 0.f;

    for (int k0 = 0; k0 < K; k0 += BK) {
        // Load A tile (64 x 32) transposed into As
        #pragma unroll
        for (int u = 0; u < 2; u++) {
            int idx = tid + u * 256;    // 512 float4
            int row = idx >> 3, kq = idx & 7;
            int grow = m0 + row;
            float4 v = make_float4(0.f, 0.f, 0.f, 0.f);
            if (grow < M)
                v = *reinterpret_cast<const float4*>(A + (size_t)grow * K + k0 + kq * 4);
            As[(kq * 4 + 0) * MT + row] = v.x;
            As[(kq * 4 + 1) * MT + row] = v.y;
            As[(kq * 4 + 2) * MT + row] = v.z;
            As[(kq * 4 + 3) * MT + row] = v.w;
        }
        // Load W tile (32 x N)
        #pragma unroll
        for (int u = 0; u < N / 32; u++) {
            int idx = tid + u * 256;
            int kk = idx / (N / 4), nq = idx % (N / 4);
            *reinterpret_cast<float4*>(&Ws[kk * N + nq * 4]) =
                *reinterpret_cast<const float4*>(W + (size_t)(k0 + kk) * N + nq * 4);
        }
        __syncthreads();

        #pragma unroll
        for (int kk = 0; kk < BK; kk++) {
            float a0 = As[kk * MT + r0 + 0];
            float a1 = As[kk * MT + r0 + 1];
            float a2 = As[kk * MT + r0 + 2];
            float a3 = As[kk * MT + r0 + 3];
            float w[TN];
            #pragma unroll
            for (int j0 = 0; j0 < TN; j0 += 4) {
                float4 wv = *reinterpret_cast<const float4*>(&Ws[kk * N + c0 + j0]);
                w[j0 + 0] = wv.x; w[j0 + 1] = wv.y; w[j0 + 2] = wv.z; w[j0 + 3] = wv.w;
            }
            #pragma unroll
            for (int j = 0; j < TN; j++) {
                acc[0 * TN + j] += a0 * w[j];
                acc[1 * TN + j] += a1 * w[j];
                acc[2 * TN + j] += a2 * w[j];
                acc[3 * TN + j] += a3 * w[j];
            }
        }
        __syncthreads();
    }

    // Epilogue
    float bvals[TN];
    if (BIAS) {
        #pragma unroll
        for (int j0 = 0; j0 < TN; j0 += 4) {
            float4 bv = *reinterpret_cast<const float4*>(bias + c0 + j0);
            bvals[j0 + 0] = bv.x; bvals[j0 + 1] = bv.y; bvals[j0 + 2] = bv.z; bvals[j0 + 3] = bv.w;
        }
    }
    #pragma unroll
    for (int i = 0; i < 4; i++) {
        int grow = m0 + r0 + i;
        if (grow >= M) continue;
        float tmp[TN];
        #pragma unroll
        for (int j = 0; j < TN; j++) {
            float v = acc[i * TN + j];
            if (BIAS) v += bvals[j];
            if (ACT) v = swishf(v);
            if (RBF) {
                float re = 0.f;
                #pragma unroll
                for (int k = 0; k < 8; k++)
                    re += r8s[(r0 + i) * 8 + k] * w2s[k * 128 + c0 + j];
                v *= re;
            }
            tmp[j] = v;
        }
        if (ADD) {
            #pragma unroll
            for (int j0 = 0; j0 < TN; j0 += 4) {
                float4 av = *reinterpret_cast<const float4*>(addsrc + (size_t)grow * N + c0 + j0);
                tmp[j0 + 0] += av.x; tmp[j0 + 1] += av.y; tmp[j0 + 2] += av.z; tmp[j0 + 3] += av.w;
            }
        }
        #pragma unroll
        for (int j0 = 0; j0 < TN; j0 += 4) {
            float4 ov = make_float4(tmp[j0], tmp[j0 + 1], tmp[j0 + 2], tmp[j0 + 3]);
            *reinterpret_cast<float4*>(out + (size_t)grow * N + c0 + j0) = ov;
        }
    }
}

// ---------------------------------------------------------------------------
// Triplet kernel: sbf_e = (sbf @ w_sbf1) @ w_sbf2;
// msg = xkjd[idx_kj] * sbf_e; agg[idx_ji] += msg (vectorized red.global.add)
// 16 triplets per 256-thread block; 16 threads (4 cols each) per triplet.
// ---------------------------------------------------------------------------
__global__ __launch_bounds__(256)
void trip_k(const float* __restrict__ sbf, const int* __restrict__ idx_kj,
            const int* __restrict__ idx_ji, const float* __restrict__ w1,
            const float* __restrict__ w2, const float* __restrict__ xkjd,
            float* __restrict__ agg, int T)
{
    __shared__ float w1s[NSBF * NBAS];   // 336
    __shared__ float w2s[NBAS * EINT];   // 512
    __shared__ float sbfs[16][NSBF];
    __shared__ float s8s[16][NBAS];

    const int tid = threadIdx.x;
    for (int i = tid; i < NSBF * NBAS; i += 256) w1s[i] = w1[i];
    for (int i = tid; i < NBAS * EINT; i += 256) w2s[i] = w2[i];

    const int local = tid >> 4;
    const int lane  = tid & 15;
    const long t = (long)blockIdx.x * 16 + local;
    const bool valid = (t < T);

    if (valid) {
        const float* sp = sbf + t * NSBF;
        for (int i = lane; i < NSBF; i += 16) sbfs[local][i] = sp[i];
    }
    __syncthreads();

    if (valid && lane < NBAS) {
        float s = 0.f;
        #pragma unroll
        for (int i = 0; i < NSBF; i++) s += sbfs[local][i] * w1s[i * NBAS + lane];
        s8s[local][lane] = s;
    }
    __syncthreads();

    if (valid) {
        const int ikj = idx_kj[t];
        const int iji = idx_ji[t];
        float4 g = *reinterpret_cast<const float4*>(xkjd + (size_t)ikj * EINT + lane * 4);
        float se[4];
        #pragma unroll
        for (int c = 0; c < 4; c++) {
            float s = 0.f;
            #pragma unroll
            for (int k = 0; k < NBAS; k++)
                s += s8s[local][k] * w2s[k * EINT + lane * 4 + c];
            se[c] = s;
        }
        float mx = g.x * se[0], my = g.y * se[1], mz = g.z * se[2], mw = g.w * se[3];
        float* p = agg + (size_t)iji * EINT + lane * 4;
        asm volatile("red.global.add.v4.f32 [%0], {%1,%2,%3,%4};"
                     :: "l"(p), "f"(mx), "f"(my), "f"(mz), "f"(mw) : "memory");
    }
}

__global__ __launch_bounds__(256)
void zero_k(float4* __restrict__ p, int n4)
{
    int i = blockIdx.x * blockDim.x + threadIdx.x;
    if (i < n4) p[i] = make_float4(0.f, 0.f, 0.f, 0.f);
}

// ---------------------------------------------------------------------------
extern "C" void kernel_launch(void* const* d_in, const int* in_sizes, int n_in,
                              void* d_out, int out_size)
{
    const float* x       = (const float*)d_in[0];
    const float* rbf     = (const float*)d_in[1];
    const float* sbf     = (const float*)d_in[2];
    const int*   idx_kj  = (const int*)  d_in[3];
    const int*   idx_ji  = (const int*)  d_in[4];
    const float* w_rbf1  = (const float*)d_in[5];
    const float* w_rbf2  = (const float*)d_in[6];
    const float* w_sbf1  = (const float*)d_in[7];
    const float* w_sbf2  = (const float*)d_in[8];
    const float* w_kj    = (const float*)d_in[9];
    const float* b_kj    = (const float*)d_in[10];
    const float* w_ji    = (const float*)d_in[11];
    const float* b_ji    = (const float*)d_in[12];
    const float* w_down  = (const float*)d_in[13];
    const float* w_up    = (const float*)d_in[14];
    const float* rb0_w1  = (const float*)d_in[15];
    const float* rb0_b1  = (const float*)d_in[16];
    const float* rb0_w2  = (const float*)d_in[17];
    const float* rb0_b2  = (const float*)d_in[18];
    const float* w_lin   = (const float*)d_in[19];
    const float* b_lin   = (const float*)d_in[20];
    const float* ra0_w1  = (const float*)d_in[21];
    const float* ra0_b1  = (const float*)d_in[22];
    const float* ra0_w2  = (const float*)d_in[23];
    const float* ra0_b2  = (const float*)d_in[24];
    const float* ra1_w1  = (const float*)d_in[25];
    const float* ra1_b1  = (const float*)d_in[26];
    const float* ra1_w2  = (const float*)d_in[27];
    const float* ra1_b2  = (const float*)d_in[28];
    float* out = (float*)d_out;

    const int E = in_sizes[0] / EHID;   // 200000
    const int T = in_sizes[3];          // 2000000

    float *bufA, *bufB, *bufC, *bufD;
    cudaGetSymbolAddress((void**)&bufA, g_bufA);
    cudaGetSymbolAddress((void**)&bufB, g_bufB);
    cudaGetSymbolAddress((void**)&bufC, g_bufC);
    cudaGetSymbolAddress((void**)&bufD, g_bufD);

    const int gE = (E + 63) / 64;

    // 1) x_ji = swish(x @ w_ji + b_ji)                       -> bufA
    gemm_k<128,128,true,true,false,false><<<gE,256>>>(x, w_ji, b_ji, nullptr, nullptr, nullptr, nullptr, bufA, E);
    // 2) t = swish(x @ w_kj + b_kj) * rbf_e                  -> bufB
    gemm_k<128,128,true,true,false,true ><<<gE,256>>>(x, w_kj, b_kj, nullptr, rbf, w_rbf1, w_rbf2, bufB, E);
    // 3) xkjd = swish(t @ w_down)                            -> bufC
    gemm_k< 64,128,false,true,false,false><<<gE,256>>>(bufB, w_down, nullptr, nullptr, nullptr, nullptr, nullptr, bufC, E);
    // 4) agg = 0
    {
        int n4 = E * EINT / 4;
        zero_k<<<(n4 + 255) / 256, 256>>>((float4*)bufD, n4);
    }
    // 5) triplet gather/scale/scatter                        -> bufD
    trip_k<<<(T + 15) / 16, 256>>>(sbf, idx_kj, idx_ji, w_sbf1, w_sbf2, bufC, bufD, T);
    // 6) h = swish(agg @ w_up) + x_ji                        -> bufB
    gemm_k<128, 64,false,true,true ,false><<<gE,256>>>(bufD, w_up, nullptr, bufA, nullptr, nullptr, nullptr, bufB, E);
    // 7) rb0: t1 = swish(h @ w1 + b1)                        -> bufA
    gemm_k<128,128,true,true,false,false><<<gE,256>>>(bufB, rb0_w1, rb0_b1, nullptr, nullptr, nullptr, nullptr, bufA, E);
    //    h = h + swish(t1 @ w2 + b2)                         -> bufB
    gemm_k<128,128,true,true,true ,false><<<gE,256>>>(bufA, rb0_w2, rb0_b2, bufB, nullptr, nullptr, nullptr, bufB, E);
    // 8) h = swish(h @ w_lin + b_lin) + x                    -> bufB (in-place A read, safe)
    gemm_k<128,128,true,true,true ,false><<<gE,256>>>(bufB, w_lin, b_lin, x, nullptr, nullptr, nullptr, bufB, E);
    // 9) ra0
    gemm_k<128,128,true,true,false,false><<<gE,256>>>(bufB, ra0_w1, ra0_b1, nullptr, nullptr, nullptr, nullptr, bufA, E);
    gemm_k<128,128,true,true,true ,false><<<gE,256>>>(bufA, ra0_w2, ra0_b2, bufB, nullptr, nullptr, nullptr, bufB, E);
    // 10) ra1 (second GEMM writes final output)
    gemm_k<128,128,true,true,false,false><<<gE,256>>>(bufB, ra1_w1, ra1_b1, nullptr, nullptr, nullptr, nullptr, bufA, E);
    gemm_k<128,128,true,true,true ,false><<<gE,256>>>(bufA, ra1_w2, ra1_b2, bufB, nullptr, nullptr, nullptr, out, E);

    (void)n_in; (void)out_size; (void)in_sizes;
}

// round 8
// speedup vs baseline: 1.8280x; 1.8280x over previous
#include <cuda_runtime.h>
#include <cstdint>
#include <cstddef>

// Problem constants (C_ prefix to avoid collisions with local identifiers)
#define C_HID 128
#define C_INT 64
#define C_BAS 8
#define C_NR 6
#define C_NSBF 42      // NS*NR = 7*6
#define C_NE 200000

// Scratch buffers (device globals; no allocation allowed)
__device__ __align__(128) float g_bufA[C_NE * C_HID];
__device__ __align__(128) float g_bufB[C_NE * C_HID];
__device__ __align__(128) float g_bufC[C_NE * C_INT];
__device__ __align__(128) float g_bufD[C_NE * C_INT];

__device__ __forceinline__ float swishf(float v) {
    return v / (1.0f + __expf(-v));
}

__device__ __forceinline__ uint32_t f2tf(float f) {
    uint32_t r;
    asm("cvt.rna.tf32.f32 %0, %1;" : "=r"(r) : "f"(f));
    return r;
}

__device__ __forceinline__ void mma_tf32(float c[4], const uint32_t a[4],
                                         uint32_t b0, uint32_t b1) {
    asm volatile(
        "mma.sync.aligned.m16n8k8.row.col.f32.tf32.tf32.f32 "
        "{%0,%1,%2,%3}, {%4,%5,%6,%7}, {%8,%9}, {%0,%1,%2,%3};"
        : "+f"(c[0]), "+f"(c[1]), "+f"(c[2]), "+f"(c[3])
        : "r"(a[0]), "r"(a[1]), "r"(a[2]), "r"(a[3]), "r"(b0), "r"(b1));
}

// ---------------------------------------------------------------------------
// TF32 tensor-core GEMM: out[M,N] = epi(A[M,K] @ W[K,N])
// epi: (+bias) -> (swish) -> (*rbf_e) -> (+addsrc)
// Block: 256 threads (8 warps, 4x2), 128-row x N tile.
// Warp tile: 32 rows x N/2 cols = 2 m16 x (N/16) n8 mma tiles.
// In-place A==out safe: each block reads only its own rows, writes in epilogue.
// ---------------------------------------------------------------------------
template<int N, int K, bool BIAS, bool ACT, bool ADD, bool RBF>
__global__ __launch_bounds__(256)
void mma_gemm(const float* __restrict__ A, const float* __restrict__ W,
              const float* __restrict__ bias, const float* __restrict__ addsrc,
              const float* __restrict__ rbf, const float* __restrict__ wrbf1,
              const float* __restrict__ wrbf2,
              float* __restrict__ out, int M)
{
    constexpr int MTILE = 128;
    constexpr int BK = 32;
    constexpr int WN = N / 2;            // cols per warp
    constexpr int NTILE = WN / 8;        // n8 tiles per warp (8 for N=128)
    constexpr int AST = BK + 4;          // A smem row stride (words) = 36
    constexpr int WST = N + 4;           // W smem row stride (words)
    static_assert(N % 16 == 0 && K % BK == 0, "shape");

    __shared__ uint32_t As[MTILE * AST]; // tf32, [row][k]
    __shared__ uint32_t Ws[BK * WST];    // tf32, [k][n]
    __shared__ float r8s[RBF ? (MTILE * 8) : 1];
    __shared__ float w2s[RBF ? (8 * 128) : 1];

    const int tid    = threadIdx.x;
    const int wid    = tid >> 5;
    const int lane   = tid & 31;
    const int g      = lane >> 2;        // 0..7
    const int tg     = lane & 3;         // 0..3
    const int warp_m = wid & 3;          // 32 rows each
    const int warp_n = wid >> 2;         // 0..1
    const int m0     = blockIdx.x * MTILE;

    // RBF prologue: r8[row] = rbf[row,:6] @ wrbf1[6,8]; stage wrbf2[8,128] (fp32)
    if (RBF) {
        #pragma unroll
        for (int u = 0; u < 4; u++) w2s[tid + u * 256] = wrbf2[tid + u * 256];
        #pragma unroll
        for (int u = 0; u < 4; u++) {
            int idx = tid + u * 256;     // 1024 = 128 rows * 8
            int row = idx >> 3, jj = idx & 7;
            int grow = m0 + row;
            float s = 0.f;
            if (grow < M) {
                #pragma unroll
                for (int i = 0; i < C_NR; i++)
                    s += rbf[(size_t)grow * C_NR + i] * wrbf1[i * 8 + jj];
            }
            r8s[row * 8 + jj] = s;
        }
    }

    float c[2][NTILE][4];
    #pragma unroll
    for (int mt = 0; mt < 2; mt++)
        #pragma unroll
        for (int nt = 0; nt < NTILE; nt++)
            #pragma unroll
            for (int i = 0; i < 4; i++) c[mt][nt][i] = 0.f;

    for (int k0 = 0; k0 < K; k0 += BK) {
        // A tile: 128 x 32 floats -> tf32 smem
        #pragma unroll
        for (int u = 0; u < 4; u++) {
            int idx = tid + u * 256;     // 1024 float4s
            int row = idx >> 3, kq = idx & 7;
            int grow = m0 + row;
            float4 v = make_float4(0.f, 0.f, 0.f, 0.f);
            if (grow < M)
                v = *reinterpret_cast<const float4*>(A + (size_t)grow * K + k0 + kq * 4);
            uint4 o = make_uint4(f2tf(v.x), f2tf(v.y), f2tf(v.z), f2tf(v.w));
            *reinterpret_cast<uint4*>(&As[row * AST + kq * 4]) = o;
        }
        // W tile: 32 x N floats -> tf32 smem
        #pragma unroll
        for (int u = 0; u < (BK * N / 4) / 256; u++) {
            int idx = tid + u * 256;
            int kk = idx / (N / 4), nq = idx % (N / 4);
            float4 v = *reinterpret_cast<const float4*>(W + (size_t)(k0 + kk) * N + nq * 4);
            uint4 o = make_uint4(f2tf(v.x), f2tf(v.y), f2tf(v.z), f2tf(v.w));
            *reinterpret_cast<uint4*>(&Ws[kk * WST + nq * 4]) = o;
        }
        __syncthreads();

        #pragma unroll
        for (int k8 = 0; k8 < BK; k8 += 8) {
            uint32_t a[2][4];
            #pragma unroll
            for (int mt = 0; mt < 2; mt++) {
                int rb = warp_m * 32 + mt * 16;
                a[mt][0] = As[(rb + g) * AST + k8 + tg];
                a[mt][1] = As[(rb + 8 + g) * AST + k8 + tg];
                a[mt][2] = As[(rb + g) * AST + k8 + tg + 4];
                a[mt][3] = As[(rb + 8 + g) * AST + k8 + tg + 4];
            }
            #pragma unroll
            for (int nt = 0; nt < NTILE; nt++) {
                int cb = warp_n * WN + nt * 8;
                uint32_t b0 = Ws[(k8 + tg) * WST + cb + g];
                uint32_t b1 = Ws[(k8 + tg + 4) * WST + cb + g];
                mma_tf32(c[0][nt], a[0], b0, b1);
                mma_tf32(c[1][nt], a[1], b0, b1);
            }
        }
        __syncthreads();
    }

    // Epilogue. c mapping: c[.][nt][0..1] -> row g,   cols tg*2, tg*2+1
    //                      c[.][nt][2..3] -> row g+8, same cols
    #pragma unroll
    for (int mt = 0; mt < 2; mt++) {
        #pragma unroll
        for (int half = 0; half < 2; half++) {
            int lrow = warp_m * 32 + mt * 16 + half * 8 + g;
            int grow = m0 + lrow;
            if (grow >= M) continue;
            #pragma unroll
            for (int nt = 0; nt < NTILE; nt++) {
                int col = warp_n * WN + nt * 8 + tg * 2;
                float v0 = c[mt][nt][half * 2 + 0];
                float v1 = c[mt][nt][half * 2 + 1];
                if (BIAS) { v0 += bias[col]; v1 += bias[col + 1]; }
                if (ACT)  { v0 = swishf(v0); v1 = swishf(v1); }
                if (RBF) {
                    float re0 = 0.f, re1 = 0.f;
                    #pragma unroll
                    for (int k = 0; k < 8; k++) {
                        float r = r8s[lrow * 8 + k];
                        re0 += r * w2s[k * 128 + col];
                        re1 += r * w2s[k * 128 + col + 1];
                    }
                    v0 *= re0; v1 *= re1;
                }
                if (ADD) {
                    float2 av = *reinterpret_cast<const float2*>(
                        addsrc + (size_t)grow * N + col);
                    v0 += av.x; v1 += av.y;
                }
                float2 ov = make_float2(v0, v1);
                *reinterpret_cast<float2*>(out + (size_t)grow * N + col) = ov;
            }
        }
    }
}

// ---------------------------------------------------------------------------
// Triplet kernel: sbf_e = (sbf @ w_sbf1) @ w_sbf2;
// msg = xkjd[idx_kj] * sbf_e; agg[idx_ji] += msg (red.global.add.v4)
// ---------------------------------------------------------------------------
__global__ __launch_bounds__(256)
void trip_k(const float* __restrict__ sbf, const int* __restrict__ idx_kj,
            const int* __restrict__ idx_ji, const float* __restrict__ w1,
            const float* __restrict__ w2, const float* __restrict__ xkjd,
            float* __restrict__ agg, int T)
{
    __shared__ float w1s[C_NSBF * C_BAS];
    __shared__ float w2s[C_BAS * C_INT];
    __shared__ float sbfs[16][C_NSBF];
    __shared__ float s8s[16][C_BAS];

    const int tid = threadIdx.x;
    for (int i = tid; i < C_NSBF * C_BAS; i += 256) w1s[i] = w1[i];
    for (int i = tid; i < C_BAS * C_INT; i += 256) w2s[i] = w2[i];

    const int local = tid >> 4;
    const int lane  = tid & 15;
    const long t = (long)blockIdx.x * 16 + local;
    const bool valid = (t < T);

    if (valid) {
        const float* sp = sbf + t * C_NSBF;
        for (int i = lane; i < C_NSBF; i += 16) sbfs[local][i] = sp[i];
    }
    __syncthreads();

    if (valid && lane < C_BAS) {
        float s = 0.f;
        #pragma unroll
        for (int i = 0; i < C_NSBF; i++) s += sbfs[local][i] * w1s[i * C_BAS + lane];
        s8s[local][lane] = s;
    }
    __syncthreads();

    if (valid) {
        const int ikj = idx_kj[t];
        const int iji = idx_ji[t];
        float4 gv = *reinterpret_cast<const float4*>(xkjd + (size_t)ikj * C_INT + lane * 4);
        float se[4];
        #pragma unroll
        for (int cc = 0; cc < 4; cc++) {
            float s = 0.f;
            #pragma unroll
            for (int k = 0; k < C_BAS; k++)
                s += s8s[local][k] * w2s[k * C_INT + lane * 4 + cc];
            se[cc] = s;
        }
        float mx = gv.x * se[0], my = gv.y * se[1], mz = gv.z * se[2], mw = gv.w * se[3];
        float* p = agg + (size_t)iji * C_INT + lane * 4;
        asm volatile("red.global.add.v4.f32 [%0], {%1,%2,%3,%4};"
                     :: "l"(p), "f"(mx), "f"(my), "f"(mz), "f"(mw) : "memory");
    }
}

__global__ __launch_bounds__(256)
void zero_k(float4* __restrict__ p, int n4)
{
    int i = blockIdx.x * blockDim.x + threadIdx.x;
    if (i < n4) p[i] = make_float4(0.f, 0.f, 0.f, 0.f);
}

// ---------------------------------------------------------------------------
extern "C" void kernel_launch(void* const* d_in, const int* in_sizes, int n_in,
                              void* d_out, int out_size)
{
    const float* x       = (const float*)d_in[0];
    const float* rbf     = (const float*)d_in[1];
    const float* sbf     = (const float*)d_in[2];
    const int*   idx_kj  = (const int*)  d_in[3];
    const int*   idx_ji  = (const int*)  d_in[4];
    const float* w_rbf1  = (const float*)d_in[5];
    const float* w_rbf2  = (const float*)d_in[6];
    const float* w_sbf1  = (const float*)d_in[7];
    const float* w_sbf2  = (const float*)d_in[8];
    const float* w_kj    = (const float*)d_in[9];
    const float* b_kj    = (const float*)d_in[10];
    const float* w_ji    = (const float*)d_in[11];
    const float* b_ji    = (const float*)d_in[12];
    const float* w_down  = (const float*)d_in[13];
    const float* w_up    = (const float*)d_in[14];
    const float* rb0_w1  = (const float*)d_in[15];
    const float* rb0_b1  = (const float*)d_in[16];
    const float* rb0_w2  = (const float*)d_in[17];
    const float* rb0_b2  = (const float*)d_in[18];
    const float* w_lin   = (const float*)d_in[19];
    const float* b_lin   = (const float*)d_in[20];
    const float* ra0_w1  = (const float*)d_in[21];
    const float* ra0_b1  = (const float*)d_in[22];
    const float* ra0_w2  = (const float*)d_in[23];
    const float* ra0_b2  = (const float*)d_in[24];
    const float* ra1_w1  = (const float*)d_in[25];
    const float* ra1_b1  = (const float*)d_in[26];
    const float* ra1_w2  = (const float*)d_in[27];
    const float* ra1_b2  = (const float*)d_in[28];
    float* out = (float*)d_out;

    const int E = in_sizes[0] / C_HID;  // 200000
    const int T = in_sizes[3];          // 2000000

    float *bufA, *bufB, *bufC, *bufD;
    cudaGetSymbolAddress((void**)&bufA, g_bufA);
    cudaGetSymbolAddress((void**)&bufB, g_bufB);
    cudaGetSymbolAddress((void**)&bufC, g_bufC);
    cudaGetSymbolAddress((void**)&bufD, g_bufD);

    const int gE = (E + 127) / 128;

    // 1) x_ji = swish(x @ w_ji + b_ji)                       -> bufA
    mma_gemm<128,128,true,true,false,false><<<gE,256>>>(x, w_ji, b_ji, nullptr, nullptr, nullptr, nullptr, bufA, E);
    // 2) t = swish(x @ w_kj + b_kj) * rbf_e                  -> bufB
    mma_gemm<128,128,true,true,false,true ><<<gE,256>>>(x, w_kj, b_kj, nullptr, rbf, w_rbf1, w_rbf2, bufB, E);
    // 3) xkjd = swish(t @ w_down)                            -> bufC
    mma_gemm< 64,128,false,true,false,false><<<gE,256>>>(bufB, w_down, nullptr, nullptr, nullptr, nullptr, nullptr, bufC, E);
    // 4) agg = 0
    {
        int n4 = E * C_INT / 4;
        zero_k<<<(n4 + 255) / 256, 256>>>((float4*)bufD, n4);
    }
    // 5) triplet gather/scale/scatter                        -> bufD
    trip_k<<<(T + 15) / 16, 256>>>(sbf, idx_kj, idx_ji, w_sbf1, w_sbf2, bufC, bufD, T);
    // 6) h = swish(agg @ w_up) + x_ji                        -> bufB
    mma_gemm<128, 64,false,true,true ,false><<<gE,256>>>(bufD, w_up, nullptr, bufA, nullptr, nullptr, nullptr, bufB, E);
    // 7) rb0
    mma_gemm<128,128,true,true,false,false><<<gE,256>>>(bufB, rb0_w1, rb0_b1, nullptr, nullptr, nullptr, nullptr, bufA, E);
    mma_gemm<128,128,true,true,true ,false><<<gE,256>>>(bufA, rb0_w2, rb0_b2, bufB, nullptr, nullptr, nullptr, bufB, E);
    // 8) h = swish(h @ w_lin + b_lin) + x
    mma_gemm<128,128,true,true,true ,false><<<gE,256>>>(bufB, w_lin, b_lin, x, nullptr, nullptr, nullptr, bufB, E);
    // 9) ra0
    mma_gemm<128,128,true,true,false,false><<<gE,256>>>(bufB, ra0_w1, ra0_b1, nullptr, nullptr, nullptr, nullptr, bufA, E);
    mma_gemm<128,128,true,true,true ,false><<<gE,256>>>(bufA, ra0_w2, ra0_b2, bufB, nullptr, nullptr, nullptr, bufB, E);
    // 10) ra1 (second GEMM writes final output)
    mma_gemm<128,128,true,true,false,false><<<gE,256>>>(bufB, ra1_w1, ra1_b1, nullptr, nullptr, nullptr, nullptr, bufA, E);
    mma_gemm<128,128,true,true,true ,false><<<gE,256>>>(bufA, ra1_w2, ra1_b2, bufB, nullptr, nullptr, nullptr, out, E);

    (void)n_in; (void)out_size; (void)in_sizes;
}

// round 13
// speedup vs baseline: 2.0086x; 1.0988x over previous
#include <cuda_runtime.h>
#include <cstdint>
#include <cstddef>

// Problem constants (C_ prefix to avoid collisions with local identifiers)
#define C_HID 128
#define C_INT 64
#define C_BAS 8
#define C_NR 6
#define C_NSBF 42      // NS*NR = 7*6
#define C_NE 200000

// Scratch buffers (device globals; no allocation allowed)
__device__ __align__(128) float g_bufA[C_NE * C_HID];
__device__ __align__(128) float g_bufB[C_NE * C_HID];
__device__ __align__(128) float g_bufC[C_NE * C_INT];
__device__ __align__(128) float g_bufD[C_NE * C_INT];

__device__ __forceinline__ float swishf(float v) {
    return v / (1.0f + __expf(-v));
}

__device__ __forceinline__ uint32_t f2tf(float f) {
    uint32_t r;
    asm("cvt.rna.tf32.f32 %0, %1;" : "=r"(r) : "f"(f));
    return r;
}

__device__ __forceinline__ void mma_tf32(float c[4], const uint32_t a[4],
                                         uint32_t b0, uint32_t b1) {
    asm volatile(
        "mma.sync.aligned.m16n8k8.row.col.f32.tf32.tf32.f32 "
        "{%0,%1,%2,%3}, {%4,%5,%6,%7}, {%8,%9}, {%0,%1,%2,%3};"
        : "+f"(c[0]), "+f"(c[1]), "+f"(c[2]), "+f"(c[3])
        : "r"(a[0]), "r"(a[1]), "r"(a[2]), "r"(a[3]), "r"(b0), "r"(b1));
}

__device__ __forceinline__ void ldsm_x4(uint32_t a[4], uint32_t byte_addr) {
    asm volatile(
        "ldmatrix.sync.aligned.m8n8.x4.shared.b16 {%0,%1,%2,%3}, [%4];"
        : "=r"(a[0]), "=r"(a[1]), "=r"(a[2]), "=r"(a[3])
        : "r"(byte_addr));
}

// ---------------------------------------------------------------------------
// TF32 tensor-core GEMM v4: out[M,N] = epi(A[M,K] @ W[K,N])
//   - W fully resident in smem; mainloop indexes row it*BK + k8 + tg
//     (v2/v3 bug: this offset was missing -> rel_err 0.21 in both)
//   - A tiles double-buffered, fragments via ldmatrix.x4 (exonerated by
//     v2==v3 identical rel_err; A-path proven equivalent to scalar v1 map)
//   - 8 warps as 2(m) x 4(n); warp tile 64 rows x N/4 cols
// epi: (+bias) -> (swish) -> (*rbf_e) -> (+addsrc)
// In-place A==out safe (reads own rows only, writes in epilogue).
// ---------------------------------------------------------------------------
template<int N, int K, bool BIAS, bool ACT, bool ADD, bool RBF>
__global__ __launch_bounds__(256)
void mma_gemm4(const float* __restrict__ A, const float* __restrict__ W,
               const float* __restrict__ bias, const float* __restrict__ addsrc,
               const float* __restrict__ rbf, const float* __restrict__ wrbf1,
               const float* __restrict__ wrbf2,
               float* __restrict__ out, int M)
{
    constexpr int MTILE = 128;
    constexpr int BK    = 32;
    constexpr int KT    = K / BK;        // k0 tiles
    constexpr int WST   = N + 8;         // W smem stride (words); conflict-free B-LDS
    constexpr int AST   = 36;            // A smem stride (words); 144B row = 9*16B, ldmatrix-aligned
    constexpr int WNN   = N / 4;         // cols per warp
    constexpr int NTn   = WNN / 8;       // n8 tiles per warp (4 for N=128, 2 for N=64)
    constexpr int ABUF  = MTILE * AST;   // words per A buffer
    static_assert(N % 32 == 0 && K % BK == 0, "shape");

    extern __shared__ uint32_t smem[];
    uint32_t* Ws = smem;                 // [K][WST]
    uint32_t* As = Ws + K * WST;         // [2][128][AST]
    float*    w2s = (float*)(As + 2 * ABUF);       // RBF: [8][128]
    float*    r8s = w2s + (RBF ? 1024 : 0);        // RBF: [128][8]

    const int tid    = threadIdx.x;
    const int wid    = tid >> 5;
    const int lane   = tid & 31;
    const int g      = lane >> 2;        // 0..7
    const int tg     = lane & 3;         // 0..3
    const int warp_m = wid & 1;          // 0..1 (64 rows each)
    const int warp_n = wid >> 1;         // 0..3 (WNN cols each)
    const int m0     = blockIdx.x * MTILE;

    // --- Load W (once, tf32, ALL K rows) ---
    #pragma unroll
    for (int u = 0; u < (K * N / 4) / 256; u++) {
        int idx = tid + u * 256;
        int kk = idx / (N / 4), nq = idx % (N / 4);
        float4 v = *reinterpret_cast<const float4*>(W + (size_t)kk * N + nq * 4);
        uint4 o = make_uint4(f2tf(v.x), f2tf(v.y), f2tf(v.z), f2tf(v.w));
        *reinterpret_cast<uint4*>(&Ws[kk * WST + nq * 4]) = o;
    }

    // --- RBF prologue ---
    if (RBF) {
        #pragma unroll
        for (int u = 0; u < 4; u++) w2s[tid + u * 256] = wrbf2[tid + u * 256];
        #pragma unroll
        for (int u = 0; u < 4; u++) {
            int idx = tid + u * 256;     // 1024 = 128 rows * 8
            int row = idx >> 3, jj = idx & 7;
            int grow = m0 + row;
            float s = 0.f;
            if (grow < M) {
                #pragma unroll
                for (int i = 0; i < C_NR; i++)
                    s += rbf[(size_t)grow * C_NR + i] * wrbf1[i * 8 + jj];
            }
            r8s[row * 8 + jj] = s;
        }
    }

    // A-stage helpers (4 float4 per thread per tile)
    const int st_row = tid >> 3;         // 0..31 (row = st_row + u*32)
    const int st_kq  = tid & 7;          // float4 within 32-k row
    float4 v[4];

    auto load_regs = [&](int k0) {
        #pragma unroll
        for (int u = 0; u < 4; u++) {
            int grow = m0 + st_row + u * 32;
            v[u] = (grow < M)
                ? *reinterpret_cast<const float4*>(A + (size_t)grow * K + k0 + st_kq * 4)
                : make_float4(0.f, 0.f, 0.f, 0.f);
        }
    };
    auto store_tile = [&](int buf) {
        uint32_t* dst = As + buf * ABUF;
        #pragma unroll
        for (int u = 0; u < 4; u++) {
            uint4 o = make_uint4(f2tf(v[u].x), f2tf(v[u].y), f2tf(v[u].z), f2tf(v[u].w));
            *reinterpret_cast<uint4*>(&dst[(st_row + u * 32) * AST + st_kq * 4]) = o;
        }
    };

    // ldmatrix per-lane address parts
    const uint32_t as_base = (uint32_t)__cvta_generic_to_shared(As);
    const int lrow_sm = lane & 15;                 // row offset within m16 tile
    const int lk_sm   = (lane >> 4) * 4;           // k offset (0 or 4)

    float c[4][NTn][4];
    #pragma unroll
    for (int mt = 0; mt < 4; mt++)
        #pragma unroll
        for (int nt = 0; nt < NTn; nt++)
            #pragma unroll
            for (int i = 0; i < 4; i++) c[mt][nt][i] = 0.f;

    // Prologue: stage tile 0
    load_regs(0);
    store_tile(0);
    __syncthreads();

    for (int it = 0; it < KT; ++it) {
        const bool has_next = (it + 1 < KT);
        if (has_next) load_regs((it + 1) * BK);

        const uint32_t buf_b = as_base + (uint32_t)((it & 1) * ABUF) * 4u;
        const uint32_t* Wb = Ws + it * BK * WST;   // <-- THE FIX: k0 row offset
        #pragma unroll
        for (int k8 = 0; k8 < BK; k8 += 8) {
            uint32_t a[4][4];
            #pragma unroll
            for (int mt = 0; mt < 4; mt++) {
                int row = warp_m * 64 + mt * 16 + lrow_sm;
                ldsm_x4(a[mt], buf_b + (uint32_t)(row * AST + k8 + lk_sm) * 4u);
            }
            #pragma unroll
            for (int nt = 0; nt < NTn; nt++) {
                int cb = warp_n * WNN + nt * 8;
                uint32_t b0 = Wb[(k8 + tg) * WST + cb + g];
                uint32_t b1 = Wb[(k8 + tg + 4) * WST + cb + g];
                #pragma unroll
                for (int mt = 0; mt < 4; mt++)
                    mma_tf32(c[mt][nt], a[mt], b0, b1);
            }
        }

        if (has_next) store_tile((it + 1) & 1);
        __syncthreads();
    }

    // Epilogue. c[mt][nt][0..1] -> row g,   cols tg*2, tg*2+1
    //           c[mt][nt][2..3] -> row g+8, same cols
    #pragma unroll
    for (int mt = 0; mt < 4; mt++) {
        #pragma unroll
        for (int half = 0; half < 2; half++) {
            int lrow = warp_m * 64 + mt * 16 + half * 8 + g;
            int grow = m0 + lrow;
            if (grow >= M) continue;
            #pragma unroll
            for (int nt = 0; nt < NTn; nt++) {
                int col = warp_n * WNN + nt * 8 + tg * 2;
                float v0 = c[mt][nt][half * 2 + 0];
                float v1 = c[mt][nt][half * 2 + 1];
                if (BIAS) { v0 += bias[col]; v1 += bias[col + 1]; }
                if (ACT)  { v0 = swishf(v0); v1 = swishf(v1); }
                if (RBF) {
                    float re0 = 0.f, re1 = 0.f;
                    #pragma unroll
                    for (int k = 0; k < 8; k++) {
                        float r = r8s[lrow * 8 + k];
                        re0 += r * w2s[k * 128 + col];
                        re1 += r * w2s[k * 128 + col + 1];
                    }
                    v0 *= re0; v1 *= re1;
                }
                if (ADD) {
                    float2 av = *reinterpret_cast<const float2*>(
                        addsrc + (size_t)grow * N + col);
                    v0 += av.x; v1 += av.y;
                }
                *reinterpret_cast<float2*>(out + (size_t)grow * N + col) =
                    make_float2(v0, v1);
            }
        }
    }
}

// ---------------------------------------------------------------------------
// Triplet kernel: sbf_e = (sbf @ w_sbf1) @ w_sbf2;
// msg = xkjd[idx_kj] * sbf_e; agg[idx_ji] += msg (red.global.add.v4)
// ---------------------------------------------------------------------------
__global__ __launch_bounds__(256)
void trip_k(const float* __restrict__ sbf, const int* __restrict__ idx_kj,
            const int* __restrict__ idx_ji, const float* __restrict__ w1,
            const float* __restrict__ w2, const float* __restrict__ xkjd,
            float* __restrict__ agg, int T)
{
    __shared__ float w1s[C_NSBF * C_BAS];
    __shared__ float w2s[C_BAS * C_INT];
    __shared__ float sbfs[16][C_NSBF];
    __shared__ float s8s[16][C_BAS];

    const int tid = threadIdx.x;
    for (int i = tid; i < C_NSBF * C_BAS; i += 256) w1s[i] = w1[i];
    for (int i = tid; i < C_BAS * C_INT; i += 256) w2s[i] = w2[i];

    const int local = tid >> 4;
    const int lane  = tid & 15;
    const long t = (long)blockIdx.x * 16 + local;
    const bool valid = (t < T);

    if (valid) {
        const float* sp = sbf + t * C_NSBF;
        for (int i = lane; i < C_NSBF; i += 16) sbfs[local][i] = sp[i];
    }
    __syncthreads();

    if (valid && lane < C_BAS) {
        float s = 0.f;
        #pragma unroll
        for (int i = 0; i < C_NSBF; i++) s += sbfs[local][i] * w1s[i * C_BAS + lane];
        s8s[local][lane] = s;
    }
    __syncthreads();

    if (valid) {
        const int ikj = idx_kj[t];
        const int iji = idx_ji[t];
        float4 gv = *reinterpret_cast<const float4*>(xkjd + (size_t)ikj * C_INT + lane * 4);
        float se[4];
        #pragma unroll
        for (int cc = 0; cc < 4; cc++) {
            float s = 0.f;
            #pragma unroll
            for (int k = 0; k < C_BAS; k++)
                s += s8s[local][k] * w2s[k * C_INT + lane * 4 + cc];
            se[cc] = s;
        }
        float mx = gv.x * se[0], my = gv.y * se[1], mz = gv.z * se[2], mw = gv.w * se[3];
        float* p = agg + (size_t)iji * C_INT + lane * 4;
        asm volatile("red.global.add.v4.f32 [%0], {%1,%2,%3,%4};"
                     :: "l"(p), "f"(mx), "f"(my), "f"(mz), "f"(mw) : "memory");
    }
}

__global__ __launch_bounds__(256)
void zero_k(float4* __restrict__ p, int n4)
{
    int i = blockIdx.x * blockDim.x + threadIdx.x;
    if (i < n4) p[i] = make_float4(0.f, 0.f, 0.f, 0.f);
}

// ---------------------------------------------------------------------------
// Host-side dynamic smem size for an instantiation
static inline int gemm4_smem_bytes(int N, int K, bool rbf) {
    int wst = N + 8;
    int words = K * wst + 2 * 128 * 36 + (rbf ? 2048 : 0);
    return words * 4;
}

extern "C" void kernel_launch(void* const* d_in, const int* in_sizes, int n_in,
                              void* d_out, int out_size)
{
    const float* x       = (const float*)d_in[0];
    const float* rbf     = (const float*)d_in[1];
    const float* sbf     = (const float*)d_in[2];
    const int*   idx_kj  = (const int*)  d_in[3];
    const int*   idx_ji  = (const int*)  d_in[4];
    const float* w_rbf1  = (const float*)d_in[5];
    const float* w_rbf2  = (const float*)d_in[6];
    const float* w_sbf1  = (const float*)d_in[7];
    const float* w_sbf2  = (const float*)d_in[8];
    const float* w_kj    = (const float*)d_in[9];
    const float* b_kj    = (const float*)d_in[10];
    const float* w_ji    = (const float*)d_in[11];
    const float* b_ji    = (const float*)d_in[12];
    const float* w_down  = (const float*)d_in[13];
    const float* w_up    = (const float*)d_in[14];
    const float* rb0_w1  = (const float*)d_in[15];
    const float* rb0_b1  = (const float*)d_in[16];
    const float* rb0_w2  = (const float*)d_in[17];
    const float* rb0_b2  = (const float*)d_in[18];
    const float* w_lin   = (const float*)d_in[19];
    const float* b_lin   = (const float*)d_in[20];
    const float* ra0_w1  = (const float*)d_in[21];
    const float* ra0_b1  = (const float*)d_in[22];
    const float* ra0_w2  = (const float*)d_in[23];
    const float* ra0_b2  = (const float*)d_in[24];
    const float* ra1_w1  = (const float*)d_in[25];
    const float* ra1_b1  = (const float*)d_in[26];
    const float* ra1_w2  = (const float*)d_in[27];
    const float* ra1_b2  = (const float*)d_in[28];
    float* out = (float*)d_out;

    const int E = in_sizes[0] / C_HID;  // 200000
    const int T = in_sizes[3];          // 2000000

    float *bufA, *bufB, *bufC, *bufD;
    cudaGetSymbolAddress((void**)&bufA, g_bufA);
    cudaGetSymbolAddress((void**)&bufB, g_bufB);
    cudaGetSymbolAddress((void**)&bufC, g_bufC);
    cudaGetSymbolAddress((void**)&bufD, g_bufD);

    const int gE = (E + 127) / 128;

    // Opt in to >48KB dynamic smem for every instantiation we use.
    const int smem_std  = gemm4_smem_bytes(128, 128, false); // 106496
    const int smem_rbf  = gemm4_smem_bytes(128, 128, true);  // 114688
    const int smem_down = gemm4_smem_bytes( 64, 128, false); //  73728
    const int smem_up   = gemm4_smem_bytes(128,  64, false); //  71680

    cudaFuncSetAttribute(mma_gemm4<128,128,true ,true,false,false>,
                         cudaFuncAttributeMaxDynamicSharedMemorySize, smem_std);
    cudaFuncSetAttribute(mma_gemm4<128,128,true ,true,true ,false>,
                         cudaFuncAttributeMaxDynamicSharedMemorySize, smem_std);
    cudaFuncSetAttribute(mma_gemm4<128,128,true ,true,false,true >,
                         cudaFuncAttributeMaxDynamicSharedMemorySize, smem_rbf);
    cudaFuncSetAttribute(mma_gemm4< 64,128,false,true,false,false>,
                         cudaFuncAttributeMaxDynamicSharedMemorySize, smem_down);
    cudaFuncSetAttribute(mma_gemm4<128, 64,false,true,true ,false>,
                         cudaFuncAttributeMaxDynamicSharedMemorySize, smem_up);

    // 0) agg = 0 (first, so ncu's fixed skip-count lands on a GEMM/trip)
    {
        int n4 = E * C_INT / 4;
        zero_k<<<(n4 + 255) / 256, 256>>>((float4*)bufD, n4);
    }
    // 1) x_ji = swish(x @ w_ji + b_ji)                       -> bufA
    mma_gemm4<128,128,true,true,false,false><<<gE,256,smem_std>>>(x, w_ji, b_ji, nullptr, nullptr, nullptr, nullptr, bufA, E);
    // 2) t = swish(x @ w_kj + b_kj) * rbf_e                  -> bufB
    mma_gemm4<128,128,true,true,false,true ><<<gE,256,smem_rbf>>>(x, w_kj, b_kj, nullptr, rbf, w_rbf1, w_rbf2, bufB, E);
    // 3) xkjd = swish(t @ w_down)                            -> bufC
    mma_gemm4< 64,128,false,true,false,false><<<gE,256,smem_down>>>(bufB, w_down, nullptr, nullptr, nullptr, nullptr, nullptr, bufC, E);
    // 4) triplet gather/scale/scatter                        -> bufD
    trip_k<<<(T + 15) / 16, 256>>>(sbf, idx_kj, idx_ji, w_sbf1, w_sbf2, bufC, bufD, T);
    // 5) h = swish(agg @ w_up) + x_ji                        -> bufB
    mma_gemm4<128, 64,false,true,true ,false><<<gE,256,smem_up>>>(bufD, w_up, nullptr, bufA, nullptr, nullptr, nullptr, bufB, E);
    // 6) rb0
    mma_gemm4<128,128,true,true,false,false><<<gE,256,smem_std>>>(bufB, rb0_w1, rb0_b1, nullptr, nullptr, nullptr, nullptr, bufA, E);
    mma_gemm4<128,128,true,true,true ,false><<<gE,256,smem_std>>>(bufA, rb0_w2, rb0_b2, bufB, nullptr, nullptr, nullptr, bufB, E);
    // 7) h = swish(h @ w_lin + b_lin) + x
    mma_gemm4<128,128,true,true,true ,false><<<gE,256,smem_std>>>(bufB, w_lin, b_lin, x, nullptr, nullptr, nullptr, bufB, E);
    // 8) ra0
    mma_gemm4<128,128,true,true,false,false><<<gE,256,smem_std>>>(bufB, ra0_w1, ra0_b1, nullptr, nullptr, nullptr, nullptr, bufA, E);
    mma_gemm4<128,128,true,true,true ,false><<<gE,256,smem_std>>>(bufA, ra0_w2, ra0_b2, bufB, nullptr, nullptr, nullptr, bufB, E);
    // 9) ra1 (second GEMM writes final output)
    mma_gemm4<128,128,true,true,false,false><<<gE,256,smem_std>>>(bufB, ra1_w1, ra1_b1, nullptr, nullptr, nullptr, nullptr, bufA, E);
    mma_gemm4<128,128,true,true,true ,false><<<gE,256,smem_std>>>(bufA, ra1_w2, ra1_b2, bufB, nullptr, nullptr, nullptr, out, E);

    (void)n_in; (void)out_size; (void)in_sizes;
}